// round 2
// baseline (speedup 1.0000x reference)
#include <cuda_runtime.h>
#include <cuda_bf16.h>
#include <math.h>
#include <stdint.h>

// ---------------- problem dims ----------------
#define BB   128
#define TT   64
#define SS   40
#define DD   256
#define HH   256
#define NG   1024          // 4*H
#define BT   (BB*TT)       // 8192

// ---------------- output layout (float32, concatenated tuple) ----------------
// final_og(256) | final_fake(256) | Dec_V(2097152) | Gen_V(2097152) | sts(8192) | label(128)
#define OG_OFF   0
#define FAKE_OFF 256
#define DEC_OFF  512
#define GEN_OFF  (DEC_OFF + BT*DD)
#define STS_OFF  (GEN_OFF + BT*DD)
#define LBL_OFF  (STS_OFF + BB*TT)

// ---------------- scratch (device globals; no allocations) ----------------
__device__ float g_v[BT*DD];         // embedded inputs  [bt][d]
__device__ float g_xg[TT*NG*BB];     // input gates      [t][g][b]
__device__ float g_h1[BT*HH];        // lstm1 h          [bt][u]
__device__ float g_h2[BT*HH];        // lstm2 h          [bt][u]
__device__ float g_wh[BT*HH];        // h1 @ Whk^T + bhk [bt][k]
__device__ float g_bar[BT*DD];       // bar_v            [bt][d]
__device__ float g_wz[BT*64];        // wh @ W1b^T       [bt][j]
__device__ float g_ez[BB*64];        // e  @ W1a^T + b1  [b][j]
__device__ float g_t1[128*1024];
__device__ float g_t2[128*512];
__device__ float g_hwork[2*HH*BB];   // double-buffered h [phase][u][b]
__device__ unsigned int g_barrier;

// =======================================================================
// embedding gather + relu + sum over S
// =======================================================================
__global__ void embed_kernel(const int* __restrict__ seqs, const float* __restrict__ emb)
{
    __shared__ int idx[SS];
    const int bv = blockIdx.x;           // 0..8191
    const int d  = threadIdx.x;          // 0..255
    if (d < SS) idx[d] = seqs[bv*SS + d];
    __syncthreads();
    float acc = 0.f;
#pragma unroll 8
    for (int s = 0; s < SS; s++) {
        float e = emb[(size_t)idx[s]*DD + d];
        acc += fmaxf(e, 0.f);
    }
    g_v[(size_t)bv*DD + d] = acc;
}

// =======================================================================
// tiled fp32 GEMM:  C = act(A @ W^T + bias [+ bias2])
//   A: [M][lda] row-major (row stride lda), rows m0 = 64*blockIdx.y
//   W: [N][ldw] row-major (row n = output col n)
//   mode 0: C[m*N + n]
//   mode 1: C[t*N*128 + n*128 + b] with b=m>>6, t=m&63   (xg layout)
//   act 1: relu
//   requires: M,N multiples of 64; K multiple of 16
// =======================================================================
#define GBM 64
#define GBN 64
#define GBK 16
__global__ void __launch_bounds__(256)
gemm_kernel(const float* __restrict__ A, int lda,
            const float* __restrict__ W, int ldw,
            const float* __restrict__ bias, const float* __restrict__ bias2,
            float* __restrict__ C, int K, int N, int mode, int act)
{
    __shared__ float As[GBK][GBM + 1];
    __shared__ float Bs[GBK][GBN + 4];
    const int m0 = blockIdx.y * GBM;
    const int n0 = blockIdx.x * GBN;
    const int tid = threadIdx.x;
    const int tx = tid & 15;           // n dir (4 cols each)
    const int ty = tid >> 4;           // m dir (4 rows each)
    const int lr  = tid >> 2;          // loader row 0..63
    const int lk4 = tid & 3;           // loader k-quad 0..3

    const float* Aload = A + (size_t)(m0 + lr) * lda + lk4 * 4;
    const float* Wload = W + (size_t)(n0 + lr) * ldw + lk4 * 4;

    float acc[4][4] = {};

    for (int k0 = 0; k0 < K; k0 += GBK) {
        float4 av = *(const float4*)(Aload + k0);
        float4 wv = *(const float4*)(Wload + k0);
        if (k0) __syncthreads();
        As[lk4*4+0][lr] = av.x; As[lk4*4+1][lr] = av.y;
        As[lk4*4+2][lr] = av.z; As[lk4*4+3][lr] = av.w;
        Bs[lk4*4+0][lr] = wv.x; Bs[lk4*4+1][lr] = wv.y;
        Bs[lk4*4+2][lr] = wv.z; Bs[lk4*4+3][lr] = wv.w;
        __syncthreads();
#pragma unroll
        for (int k = 0; k < GBK; k++) {
            float a0 = As[k][ty*4+0];
            float a1 = As[k][ty*4+1];
            float a2 = As[k][ty*4+2];
            float a3 = As[k][ty*4+3];
            float4 bv = *(const float4*)&Bs[k][tx*4];
            acc[0][0] = fmaf(a0, bv.x, acc[0][0]);
            acc[0][1] = fmaf(a0, bv.y, acc[0][1]);
            acc[0][2] = fmaf(a0, bv.z, acc[0][2]);
            acc[0][3] = fmaf(a0, bv.w, acc[0][3]);
            acc[1][0] = fmaf(a1, bv.x, acc[1][0]);
            acc[1][1] = fmaf(a1, bv.y, acc[1][1]);
            acc[1][2] = fmaf(a1, bv.z, acc[1][2]);
            acc[1][3] = fmaf(a1, bv.w, acc[1][3]);
            acc[2][0] = fmaf(a2, bv.x, acc[2][0]);
            acc[2][1] = fmaf(a2, bv.y, acc[2][1]);
            acc[2][2] = fmaf(a2, bv.z, acc[2][2]);
            acc[2][3] = fmaf(a2, bv.w, acc[2][3]);
            acc[3][0] = fmaf(a3, bv.x, acc[3][0]);
            acc[3][1] = fmaf(a3, bv.y, acc[3][1]);
            acc[3][2] = fmaf(a3, bv.z, acc[3][2]);
            acc[3][3] = fmaf(a3, bv.w, acc[3][3]);
        }
    }

#pragma unroll
    for (int i = 0; i < 4; i++) {
#pragma unroll
        for (int j = 0; j < 4; j++) {
            int m = m0 + ty*4 + i;
            int n = n0 + tx*4 + j;
            float val = acc[i][j];
            if (bias)  val += bias[n];
            if (bias2) val += bias2[n];
            if (act) val = fmaxf(val, 0.f);
            if (mode == 0) {
                C[(size_t)m * N + n] = val;
            } else {
                int b = m >> 6, t = m & 63;
                C[(size_t)t * (N*128) + (size_t)n * 128 + b] = val;
            }
        }
    }
}

// =======================================================================
// persistent LSTM: 128 blocks (2 hidden units each), 256 threads
// xg: [t][g][b], Whh: [1024][256], h_all out: [bt][u]
// =======================================================================
#define LSTM_SMEM ((HH*BB + HH*8) * 4)   // h_sm[j][b] + w_sm[j][p][q]

__global__ void reset_kernel() { if (threadIdx.x == 0) g_barrier = 0u; }

__global__ void __launch_bounds__(256, 1)
lstm_kernel(const float* __restrict__ xg,
            const float* __restrict__ Whh,
            float* __restrict__ h_all)
{
    extern __shared__ float sm[];
    float* h_sm = sm;              // [256][128] : h_sm[j*128 + b]
    float* w_sm = sm + HH*BB;      // [256][2][4]: w_sm[j*8 + p*4 + q]
    const int tid = threadIdx.x;
    const int u0  = blockIdx.x * 2;
    const int b   = tid >> 1;
    const int p   = tid & 1;
    const int u   = u0 + p;

    // pack W_hh rows for our 8 gate-rows: w_sm[j*8 + p*4 + q] = Whh[q*256+u0+p][j]
    for (int idx = tid; idx < HH*8; idx += 256) {
        int j = idx >> 3, r = idx & 7, pp = r >> 2, q = r & 3;
        w_sm[idx] = Whh[(size_t)(q*HH + u0 + pp)*HH + j];
    }
    for (int i = tid; i < HH*BB; i += 256) h_sm[i] = 0.f;
    float c = 0.f;
    unsigned target = 128;
    __syncthreads();

    for (int t = 0; t < TT; t++) {
        float a0 = 0.f, a1 = 0.f, a2 = 0.f, a3 = 0.f;
#pragma unroll 8
        for (int j = 0; j < HH; j++) {
            float hv = h_sm[j*BB + b];
            float4 w = *(const float4*)&w_sm[j*8 + p*4];
            a0 = fmaf(hv, w.x, a0);
            a1 = fmaf(hv, w.y, a1);
            a2 = fmaf(hv, w.z, a2);
            a3 = fmaf(hv, w.w, a3);
        }
        const float* xgt = xg + (size_t)t * (NG*BB);
        float gi = a0 + xgt[(0*HH + u)*BB + b];
        float gf = a1 + xgt[(1*HH + u)*BB + b];
        float gg = a2 + xgt[(2*HH + u)*BB + b];
        float go = a3 + xgt[(3*HH + u)*BB + b];
        float iv = 1.f / (1.f + expf(-gi));
        float fv = 1.f / (1.f + expf(-gf));
        float gv = tanhf(gg);
        float ov = 1.f / (1.f + expf(-go));
        c = fv * c + iv * gv;
        float h = ov * tanhf(c);

        h_all[((size_t)b*TT + t)*HH + u] = h;
        float* hw = g_hwork + (t & 1) * (HH*BB);
        hw[u*BB + b] = h;

        // grid barrier (arrive + spin), release via threadfence
        __syncthreads();
        if (tid == 0) {
            __threadfence();
            atomicAdd(&g_barrier, 1u);
            volatile unsigned* bar = (volatile unsigned*)&g_barrier;
            while (*bar < target) { }
        }
        __syncthreads();
        target += 128;

        // stage full h into smem; bypass L1 (not coherent across SMs)
        const float4* src = (const float4*)hw;
        float4* dst = (float4*)h_sm;
        for (int i = tid; i < (HH*BB)/4; i += 256) dst[i] = __ldcg(&src[i]);
        __syncthreads();
    }
}

// =======================================================================
// attention finalize: per (b, t=0..62), softmax over 2 and blend
// =======================================================================
__global__ void attn_kernel(const float* __restrict__ W2,
                            const float* __restrict__ b2,
                            float* __restrict__ out)
{
    const int idx = blockIdx.x;        // 0..8063
    const int b = idx / 63;
    const int t = idx % 63;
    const int tid = threadIdx.x;
    __shared__ float z1[64];
    __shared__ float a01[2];

    if (tid < 64) {
        float z = g_ez[b*64 + tid] + g_wz[((size_t)b*TT + t)*64 + tid];
        z1[tid] = tanhf(z);
    }
    __syncthreads();
    if (tid < 32) {
        float x0 = z1[tid], x1 = z1[tid + 32];
        float s0 = x0 * W2[tid]      + x1 * W2[tid + 32];
        float s1 = x0 * W2[64 + tid] + x1 * W2[96 + tid];
#pragma unroll
        for (int off = 16; off; off >>= 1) {
            s0 += __shfl_xor_sync(0xffffffffu, s0, off);
            s1 += __shfl_xor_sync(0xffffffffu, s1, off);
        }
        if (tid == 0) {
            s0 += b2[0]; s1 += b2[1];
            float m = fmaxf(s0, s1);
            float e0 = expf(s0 - m), e1 = expf(s1 - m);
            float inv = 1.f / (e0 + e1);
            a01[0] = e0 * inv; a01[1] = e1 * inv;
        }
    }
    __syncthreads();
    float e = g_v[(size_t)b*TT*DD + tid];                    // v[b][0][d]
    float w = g_wh[((size_t)b*TT + t)*HH + tid];             // wh_prev
    float bv = e * a01[0] + w * a01[1];
    size_t o = ((size_t)b*TT + t + 1)*DD + tid;
    g_bar[o] = bv;
    out[DEC_OFF + o] = bv;
    out[GEN_OFF + o] = bv;
}

// =======================================================================
// passthroughs: bar_v row t=0, seq_time_step, label
// =======================================================================
__global__ void tail_kernel(const float* __restrict__ sts,
                            const int* __restrict__ label,
                            float* __restrict__ out)
{
    const int b = blockIdx.x, tid = threadIdx.x;
    float val = g_v[(size_t)b*TT*DD + tid];
    size_t o = (size_t)b*TT*DD + tid;
    g_bar[o] = val;
    out[DEC_OFF + o] = val;
    out[GEN_OFF + o] = val;
    if (tid < TT) out[STS_OFF + b*TT + tid] = sts[b*TT + tid];
    if (tid == 0) out[LBL_OFF + b] = (float)label[b];
}

// =======================================================================
// warp-per-output FC (for the tiny N=2 head): C = A @ W^T + bias
// =======================================================================
__global__ void fc_kernel(const float* __restrict__ A, int lda,
                          const float* __restrict__ W, int ldw,
                          const float* __restrict__ bias,
                          float* __restrict__ C, int ldc,
                          int M, int N, int K)
{
    int gw = (blockIdx.x * blockDim.x + threadIdx.x) >> 5;
    int lane = threadIdx.x & 31;
    if (gw >= M * N) return;
    int m = gw / N, n = gw % N;
    const float* a = A + (size_t)m * lda;
    const float* w = W + (size_t)n * ldw;
    float acc = 0.f;
    for (int k = lane * 4; k < K; k += 128) {
        float4 av = *(const float4*)(a + k);
        float4 wv = *(const float4*)(w + k);
        acc += av.x*wv.x + av.y*wv.y + av.z*wv.z + av.w*wv.w;
    }
#pragma unroll
    for (int off = 16; off; off >>= 1) acc += __shfl_xor_sync(0xffffffffu, acc, off);
    if (lane == 0) C[(size_t)m * ldc + n] = acc + bias[n];
}

// =======================================================================
// host launcher
// =======================================================================
extern "C" void kernel_launch(void* const* d_in, const int* in_sizes, int n_in,
                              void* d_out, int out_size)
{
    (void)in_sizes; (void)n_in; (void)out_size;
    const int*   seqs  = (const int*)  d_in[0];
    const float* sts   = (const float*)d_in[3];
    const int*   label = (const int*)  d_in[5];
    const float* emb   = (const float*)d_in[6];
    const float* W_ih  = (const float*)d_in[7];
    const float* W_hh  = (const float*)d_in[8];
    const float* b_ih  = (const float*)d_in[9];
    const float* b_hh  = (const float*)d_in[10];
    const float* Whk   = (const float*)d_in[11];
    const float* bhk   = (const float*)d_in[12];
    const float* W1    = (const float*)d_in[13];
    const float* b1    = (const float*)d_in[14];
    const float* W2    = (const float*)d_in[15];
    const float* b2    = (const float*)d_in[16];
    const float* C1W   = (const float*)d_in[17];
    const float* C1b   = (const float*)d_in[18];
    const float* C2W   = (const float*)d_in[19];
    const float* C2b   = (const float*)d_in[20];
    const float* CoW   = (const float*)d_in[21];
    const float* Cob   = (const float*)d_in[22];
    float* out = (float*)d_out;

    cudaFuncSetAttribute(lstm_kernel, cudaFuncAttributeMaxDynamicSharedMemorySize, LSTM_SMEM);

    float *p_v, *p_xg, *p_h1, *p_h2, *p_wh, *p_bar, *p_wz, *p_ez, *p_t1, *p_t2;
    cudaGetSymbolAddress((void**)&p_v,   g_v);
    cudaGetSymbolAddress((void**)&p_xg,  g_xg);
    cudaGetSymbolAddress((void**)&p_h1,  g_h1);
    cudaGetSymbolAddress((void**)&p_h2,  g_h2);
    cudaGetSymbolAddress((void**)&p_wh,  g_wh);
    cudaGetSymbolAddress((void**)&p_bar, g_bar);
    cudaGetSymbolAddress((void**)&p_wz,  g_wz);
    cudaGetSymbolAddress((void**)&p_ez,  g_ez);
    cudaGetSymbolAddress((void**)&p_t1,  g_t1);
    cudaGetSymbolAddress((void**)&p_t2,  g_t2);

    // 1. embed
    embed_kernel<<<BT, 256>>>(seqs, emb);

    // 2. xg1 = v @ W_ih^T + b_ih + b_hh   -> [t][g][b]
    gemm_kernel<<<dim3(NG/64, BT/64), 256>>>(p_v, DD, W_ih, DD, b_ih, b_hh,
                                             p_xg, DD, NG, 1, 0);
    // 3. LSTM1
    reset_kernel<<<1, 32>>>();
    lstm_kernel<<<128, 256, LSTM_SMEM>>>(p_xg, W_hh, p_h1);

    // 4. wh = h1 @ Whk^T + bhk
    gemm_kernel<<<dim3(HH/64, BT/64), 256>>>(p_h1, HH, Whk, HH, bhk, nullptr,
                                             p_wh, HH, HH, 0, 0);
    // 5. wz = wh @ W1[:,256:]^T
    gemm_kernel<<<dim3(1, BT/64), 256>>>(p_wh, HH, W1 + 256, 512, nullptr, nullptr,
                                         p_wz, HH, 64, 0, 0);
    // 6. ez = v[:,0,:] @ W1[:,:256]^T + b1
    gemm_kernel<<<dim3(1, 2), 256>>>(p_v, TT*DD, W1, 512, b1, nullptr,
                                     p_ez, DD, 64, 0, 0);
    // 7. bar_v rows t=1..63 + outputs Dec/Gen; row t=0 + passthroughs
    attn_kernel<<<BB*63, 256>>>(W2, b2, out);
    tail_kernel<<<BB, 256>>>(sts, label, out);

    // 8. xg2 = bar_v @ W_ih^T + b_ih + b_hh
    gemm_kernel<<<dim3(NG/64, BT/64), 256>>>(p_bar, DD, W_ih, DD, b_ih, b_hh,
                                             p_xg, DD, NG, 1, 0);
    // 9. LSTM2
    reset_kernel<<<1, 32>>>();
    lstm_kernel<<<128, 256, LSTM_SMEM>>>(p_xg, W_hh, p_h2);

    // 10. classify og (h1 at t=63)
    gemm_kernel<<<dim3(1024/64, 2), 256>>>(p_h1 + 63*HH, TT*HH, C1W, HH, C1b, nullptr,
                                           p_t1, HH, 1024, 0, 1);
    gemm_kernel<<<dim3(512/64, 2), 256>>>(p_t1, 1024, C2W, 1024, C2b, nullptr,
                                          p_t2, 1024, 512, 0, 1);
    fc_kernel<<<(128*2*32 + 255)/256, 256>>>(p_t2, 512, CoW, 512, Cob,
                                             out + OG_OFF, 2, 128, 2, 512);

    // 11. classify fake (h2 at t=63)
    gemm_kernel<<<dim3(1024/64, 2), 256>>>(p_h2 + 63*HH, TT*HH, C1W, HH, C1b, nullptr,
                                           p_t1, HH, 1024, 0, 1);
    gemm_kernel<<<dim3(512/64, 2), 256>>>(p_t1, 1024, C2W, 1024, C2b, nullptr,
                                          p_t2, 1024, 512, 0, 1);
    fc_kernel<<<(128*2*32 + 255)/256, 256>>>(p_t2, 512, CoW, 512, Cob,
                                             out + FAKE_OFF, 2, 128, 2, 512);
}